// round 2
// baseline (speedup 1.0000x reference)
#include <cuda_runtime.h>
#include <cstdint>

// ---------------------------------------------------------------------------
// Scratch buffers (static __device__ globals — no allocation allowed).
// ---------------------------------------------------------------------------
__device__ float g_bufA[33554432];
__device__ float g_bufB[67108864];
__device__ float g_bufC[33554432];

// Packed 2-wide fp32 FMA (sm_103a FFMA2) — only reachable via PTX.
__device__ __forceinline__ unsigned long long fma2(unsigned long long a,
                                                   unsigned long long b,
                                                   unsigned long long c)
{
    unsigned long long d;
    asm("fma.rn.f32x2 %0, %1, %2, %3;" : "=l"(d) : "l"(a), "l"(b), "l"(c));
    return d;
}

__device__ __forceinline__ unsigned long long bcast2(float v)
{
    unsigned long long d;
    asm("mov.b64 %0, {%1, %1};" : "=l"(d) : "f"(v));
    return d;
}

__device__ __forceinline__ unsigned long long pack2(float lo, float hi)
{
    unsigned long long d;
    asm("mov.b64 %0, {%1, %2};" : "=l"(d) : "f"(lo), "f"(hi));
    return d;
}

__device__ __forceinline__ float2 unpack2(unsigned long long v)
{
    float2 r;
    asm("mov.b64 {%0, %1}, %2;" : "=f"(r.x), "=f"(r.y) : "l"(v));
    return r;
}

// ---------------------------------------------------------------------------
// Direct 3x3 conv, pad=1, stride templated. NCHW / OIHW, cross-correlation.
// Block (8,16)=128 thr. Per block: 32(w) x 16(h) output tile, one image,
// 8 output channels. Per thread: 4 px x 4 channel-PAIRS via fma.rn.f32x2.
// Weights in smem interleaved as float2 (co_even, co_odd), layout
// [ci][copair][k] so inner loop uses immediate-offset LDS.64.
// ---------------------------------------------------------------------------
template<int STRIDE>
__global__ __launch_bounds__(128)
void conv3x3_f2_kernel(const float* __restrict__ in, const float* __restrict__ w,
                       const float* __restrict__ bias, float* __restrict__ out,
                       int Cin, int Cout, int Hin, int Win, int do_relu)
{
    constexpr int TW = 32, TH = 16;
    constexpr int TIW  = TW * STRIDE + 2;          // 34 / 66
    constexpr int TIWP = (TIW + 3) & ~3;           // 36 / 68 (16B-aligned rows)
    constexpr int TIH  = TH * STRIDE + 2;          // 18 / 34
    constexpr int COG  = 8;
    constexpr int NCP  = COG / 2;                  // 4 channel pairs
    constexpr int NIN  = 4 * STRIDE + 2;           // inputs per thread-row

    __shared__ __align__(16) float s_tile[TIH * TIWP];
    __shared__ float2 s_wp[64 * NCP * 9];          // Cin up to 64: 18432 B

    const int Hout = Hin / STRIDE, Wout = Win / STRIDE;
    const int tx = threadIdx.x;                    // 0..7
    const int ty = threadIdx.y;                    // 0..15
    const int tid = ty * 8 + tx;
    const int groups = Cout / COG;
    const int g = blockIdx.z % groups;
    const int b = blockIdx.z / groups;

    // Preload weights, interleaving channel pairs: s_wp[(ci*NCP+cp)*9+k]
    {
        const int wn = NCP * Cin * 9;
        for (int i = tid; i < wn; i += 128) {
            int k  = i % 9;
            int r2 = i / 9;
            int cp = r2 % NCP;
            int ci = r2 / NCP;
            int co0 = g * COG + 2 * cp;
            s_wp[i] = make_float2(w[((size_t)co0 * Cin + ci) * 9 + k],
                                  w[((size_t)(co0 + 1) * Cin + ci) * 9 + k]);
        }
    }

    unsigned long long acc[NCP][4];
    #pragma unroll
    for (int cp = 0; cp < NCP; cp++) {
        float b0 = bias ? bias[g * COG + 2 * cp]     : 0.0f;
        float b1 = bias ? bias[g * COG + 2 * cp + 1] : 0.0f;
        unsigned long long bp = pack2(b0, b1);
        #pragma unroll
        for (int px = 0; px < 4; px++) acc[cp][px] = bp;
    }

    const int y0 = blockIdx.y * TH * STRIDE - 1;
    const int x0 = blockIdx.x * TW * STRIDE - 1;

    const float* trow_base = s_tile + ty * STRIDE * TIWP + tx * 4 * STRIDE;

    for (int ci = 0; ci < Cin; ci++) {
        __syncthreads();   // s_tile reuse guard (also covers weight preload)
        const float* ip = in + ((size_t)b * Cin + ci) * ((size_t)Hin * Win);
        for (int r = ty; r < TIH; r += 16) {
            int gy = y0 + r;
            bool yok = (gy >= 0) & (gy < Hin);
            const float* row = ip + (size_t)gy * Win;
            float* srow = s_tile + r * TIWP;
            for (int c = tx; c < TIW; c += 8) {
                int gx = x0 + c;
                srow[c] = (yok && gx >= 0 && gx < Win) ? __ldg(row + gx) : 0.0f;
            }
        }
        __syncthreads();

        const float2* wrow = s_wp + ci * (NCP * 9);

        #pragma unroll
        for (int dy = 0; dy < 3; dy++) {
            // Vector-load this thread's input row, broadcast-pack each value.
            unsigned long long bc[NIN];
            {
                const float4* t4 = reinterpret_cast<const float4*>(trow_base + dy * TIWP);
                float4 a = t4[0];
                bc[0] = bcast2(a.x); bc[1] = bcast2(a.y);
                bc[2] = bcast2(a.z); bc[3] = bcast2(a.w);
                if (STRIDE == 2) {
                    float4 e = t4[1];
                    bc[4] = bcast2(e.x); bc[5] = bcast2(e.y);
                    bc[6] = bcast2(e.z); bc[7] = bcast2(e.w);
                    float2 t = *reinterpret_cast<const float2*>(trow_base + dy * TIWP + 8);
                    bc[NIN - 2] = bcast2(t.x); bc[NIN - 1] = bcast2(t.y);
                } else {
                    float2 t = *reinterpret_cast<const float2*>(trow_base + dy * TIWP + 4);
                    bc[NIN - 2] = bcast2(t.x); bc[NIN - 1] = bcast2(t.y);
                }
            }

            #pragma unroll
            for (int cp = 0; cp < NCP; cp++) {
                const float2* wp = wrow + cp * 9 + dy * 3;
                float2 w0f = wp[0], w1f = wp[1], w2f = wp[2];
                unsigned long long W0 = *reinterpret_cast<unsigned long long*>(&w0f);
                unsigned long long W1 = *reinterpret_cast<unsigned long long*>(&w1f);
                unsigned long long W2 = *reinterpret_cast<unsigned long long*>(&w2f);
                #pragma unroll
                for (int px = 0; px < 4; px++) {
                    acc[cp][px] = fma2(bc[px * STRIDE + 0], W0, acc[cp][px]);
                    acc[cp][px] = fma2(bc[px * STRIDE + 1], W1, acc[cp][px]);
                    acc[cp][px] = fma2(bc[px * STRIDE + 2], W2, acc[cp][px]);
                }
            }
        }
    }

    const int oy = blockIdx.y * TH + ty;
    const int ox = blockIdx.x * TW + tx * 4;
    #pragma unroll
    for (int cp = 0; cp < NCP; cp++) {
        float o0[4], o1[4];
        #pragma unroll
        for (int px = 0; px < 4; px++) {
            float2 v = unpack2(acc[cp][px]);
            o0[px] = v.x; o1[px] = v.y;
        }
        if (do_relu) {
            #pragma unroll
            for (int px = 0; px < 4; px++) {
                o0[px] = fmaxf(o0[px], 0.0f);
                o1[px] = fmaxf(o1[px], 0.0f);
            }
        }
        int co0 = g * COG + 2 * cp;
        *reinterpret_cast<float4*>(
            out + (((size_t)b * Cout + co0) * Hout + oy) * Wout + ox) =
            make_float4(o0[0], o0[1], o0[2], o0[3]);
        *reinterpret_cast<float4*>(
            out + (((size_t)b * Cout + co0 + 1) * Hout + oy) * Wout + ox) =
            make_float4(o1[0], o1[1], o1[2], o1[3]);
    }
}

// ---------------------------------------------------------------------------
// ConvOffset2D bilinear sampling (faithful torch-style raw reshape).
// ---------------------------------------------------------------------------
__global__ void deform_kernel(const float* __restrict__ x,
                              const float* __restrict__ off,
                              float* __restrict__ out,
                              int C, int H, int W, int total)
{
    int idx = blockIdx.x * blockDim.x + threadIdx.x;
    if (idx >= total) return;
    int w = idx % W;
    int h = (idx / W) % H;
    int c = (idx / (W * H)) % C;
    int b = idx / (W * H * C);

    size_t HW = (size_t)H * W;
    size_t obase = ((size_t)b * 2 * C + 2 * c) * HW + 2 * ((size_t)h * W + w);
    float o0 = off[obase];
    float o1 = off[obase + 1];

    float r  = fminf(fmaxf(o0 + (float)h, 0.0f), (float)(H - 1));
    float cc = fminf(fmaxf(o1 + (float)w, 0.0f), (float)(W - 1));
    float r0f = floorf(r), c0f = floorf(cc);
    int r0 = (int)r0f;
    int r1 = (int)ceilf(r);
    int c0 = (int)c0f;
    int c1 = (int)ceilf(cc);

    const float* xb = x + ((size_t)b * C + c) * HW;
    float v_lt = xb[(size_t)r0 * W + c0];
    float v_rb = xb[(size_t)r1 * W + c1];
    float v_lb = xb[(size_t)r0 * W + c1];
    float v_rt = xb[(size_t)r1 * W + c0];
    float fr = r - r0f;
    float fc = cc - c0f;
    float vt = v_lt + (v_rt - v_lt) * fr;
    float vb = v_lb + (v_rb - v_lb) * fr;
    out[idx] = vt + (vb - vt) * fc;
}

// ---------------------------------------------------------------------------
// Global average pool over H*W. One block per (b, c).
// ---------------------------------------------------------------------------
__global__ void avgpool_kernel(const float* __restrict__ in,
                               float* __restrict__ out, int HW)
{
    const float* p = in + (size_t)blockIdx.x * HW;
    float s = 0.0f;
    for (int i = threadIdx.x; i < HW; i += blockDim.x) s += p[i];
    __shared__ float sm[256];
    sm[threadIdx.x] = s;
    __syncthreads();
    for (int st = 128; st > 0; st >>= 1) {
        if (threadIdx.x < st) sm[threadIdx.x] += sm[threadIdx.x + st];
        __syncthreads();
    }
    if (threadIdx.x == 0) out[blockIdx.x] = sm[0] / (float)HW;
}

// ---------------------------------------------------------------------------
// Launch pipeline (graph-capturable: kernel launches only).
// ---------------------------------------------------------------------------
extern "C" void kernel_launch(void* const* d_in, const int* in_sizes, int n_in,
                              void* d_out, int out_size)
{
    const float* x   = (const float*)d_in[0];
    const float* w1  = (const float*)d_in[1];
    const float* b1  = (const float*)d_in[2];
    const float* ow1 = (const float*)d_in[3];
    const float* w2  = (const float*)d_in[4];
    const float* b2  = (const float*)d_in[5];
    const float* ow2 = (const float*)d_in[6];
    const float* w3  = (const float*)d_in[7];
    const float* b3  = (const float*)d_in[8];
    const float* ow3 = (const float*)d_in[9];
    const float* w4  = (const float*)d_in[10];
    const float* b4  = (const float*)d_in[11];
    float* outp = (float*)d_out;

    float *A, *B, *C;
    cudaGetSymbolAddress((void**)&A, g_bufA);
    cudaGetSymbolAddress((void**)&B, g_bufB);
    cudaGetSymbolAddress((void**)&C, g_bufC);

    const dim3 blk(8, 16);

    // 1) conv1: x(16,32,256,256) -> A, relu
    conv3x3_f2_kernel<1><<<dim3(8, 16, 16 * 4), blk>>>(x, w1, b1, A, 32, 32, 256, 256, 1);

    // 2) offconv1: A -> B (16,64,256,256)
    conv3x3_f2_kernel<1><<<dim3(8, 16, 16 * 8), blk>>>(A, ow1, nullptr, B, 32, 64, 256, 256, 0);

    // 3) deform1: A,B -> C (16,32,256,256)
    {
        int total = 16 * 32 * 256 * 256;
        deform_kernel<<<total / 256, 256>>>(A, B, C, 32, 256, 256, total);
    }

    // 4) conv2 stride2: C -> A (16,64,128,128), relu
    conv3x3_f2_kernel<2><<<dim3(4, 8, 16 * 8), blk>>>(C, w2, b2, A, 32, 64, 256, 256, 1);

    // 5) offconv2: A -> B (16,128,128,128)
    conv3x3_f2_kernel<1><<<dim3(4, 8, 16 * 16), blk>>>(A, ow2, nullptr, B, 64, 128, 128, 128, 0);

    // 6) deform2: A,B -> C (16,64,128,128)
    {
        int total = 16 * 64 * 128 * 128;
        deform_kernel<<<total / 256, 256>>>(A, B, C, 64, 128, 128, total);
    }

    // 7) conv3 stride2: C -> A (16,32,64,64), relu
    conv3x3_f2_kernel<2><<<dim3(2, 4, 16 * 4), blk>>>(C, w3, b3, A, 64, 32, 128, 128, 1);

    // 8) offconv3: A -> B (16,64,64,64)
    conv3x3_f2_kernel<1><<<dim3(2, 4, 16 * 8), blk>>>(A, ow3, nullptr, B, 32, 64, 64, 64, 0);

    // 9) deform3: A,B -> C (16,32,64,64)
    {
        int total = 16 * 32 * 64 * 64;
        deform_kernel<<<total / 256, 256>>>(A, B, C, 32, 64, 64, total);
    }

    // 10) conv4 stride2: C -> A (16,32,32,32), relu
    conv3x3_f2_kernel<2><<<dim3(1, 2, 16 * 4), blk>>>(C, w4, b4, A, 32, 32, 64, 64, 1);

    // 11) global avg pool -> (16,32,1,1)
    avgpool_kernel<<<512, 256>>>(A, outp, 32 * 32);
}

// round 3
// speedup vs baseline: 1.0113x; 1.0113x over previous
#include <cuda_runtime.h>
#include <cstdint>

// ---------------------------------------------------------------------------
// Scratch buffers (static __device__ globals — no allocation allowed).
// ---------------------------------------------------------------------------
__device__ float g_bufA[33554432];
__device__ float g_bufB[67108864];
__device__ float g_bufC[33554432];

// ---------------------------------------------------------------------------
// Direct 3x3 conv, pad=1. NCHW / OIHW, cross-correlation.
// Block (8,16)=128 thr. Per block: 32(w) x 16(h) outputs, one image, 8 couts.
// Per thread: 4 px x 8 co = 32 fp32 accumulators.
// Weight smem layout [ci][k][co] (co contiguous) -> broadcast LDS.128.
// All trip counts / strides compile-time (STRIDE, CIN templated).
// ---------------------------------------------------------------------------
template<int STRIDE, int CIN>
__global__ __launch_bounds__(128)
void conv3x3_kernel(const float* __restrict__ in, const float* __restrict__ w,
                    const float* __restrict__ bias, float* __restrict__ out,
                    int Cout, int Hin, int Win, int do_relu)
{
    constexpr int TW = 32, TH = 16;
    constexpr int TIW  = TW * STRIDE + 2;          // 34 / 66
    constexpr int TIWP = (TIW + 3) & ~3;           // 36 / 68 (16B-aligned rows)
    constexpr int TIH  = TH * STRIDE + 2;          // 18 / 34
    constexpr int COG  = 8;
    constexpr int NIN  = 4 * STRIDE + 2;           // inputs per thread-row

    __shared__ __align__(16) float s_tile[TIH * TIWP];
    __shared__ __align__(16) float s_w[CIN * 9 * COG];

    const int Hout = Hin / STRIDE, Wout = Win / STRIDE;
    const int tx = threadIdx.x;                    // 0..7
    const int ty = threadIdx.y;                    // 0..15
    const int tid = ty * 8 + tx;
    const int groups = Cout / COG;
    const int g = blockIdx.z % groups;
    const int b = blockIdx.z / groups;

    // Preload weights into [ci][k][co] layout (one-time cost).
    {
        constexpr int WN = CIN * 9 * COG;
        #pragma unroll 4
        for (int i = tid; i < WN; i += 128) {
            int co = i & 7;
            int k  = (i >> 3) % 9;
            int ci = i / 72;
            s_w[i] = w[(((size_t)(g * COG + co)) * CIN + ci) * 9 + k];
        }
    }

    float acc[COG][4];
    #pragma unroll
    for (int co = 0; co < COG; co++) {
        float bv = bias ? bias[g * COG + co] : 0.0f;
        #pragma unroll
        for (int px = 0; px < 4; px++) acc[co][px] = bv;
    }

    const int y0 = blockIdx.y * TH * STRIDE - 1;
    const int x0 = blockIdx.x * TW * STRIDE - 1;
    const float* trow_base = s_tile + ty * STRIDE * TIWP + tx * 4 * STRIDE;
    const float* ip0 = in + (size_t)b * CIN * ((size_t)Hin * Win);

    for (int ci = 0; ci < CIN; ci++) {
        __syncthreads();   // s_tile reuse guard (also covers weight preload)
        const float* ip = ip0 + (size_t)ci * Hin * Win;
        #pragma unroll
        for (int r = ty; r < TIH; r += 16) {
            const int gy = y0 + r;
            const bool yok = (gy >= 0) & (gy < Hin);
            const float* row = ip + (size_t)gy * Win;
            float* srow = s_tile + r * TIWP;
            #pragma unroll
            for (int c = tx; c < TIW; c += 8) {
                const int gx = x0 + c;
                srow[c] = (yok && gx >= 0 && gx < Win) ? __ldg(row + gx) : 0.0f;
            }
        }
        __syncthreads();

        const float4* wk = reinterpret_cast<const float4*>(s_w + ci * 72);

        #pragma unroll
        for (int dy = 0; dy < 3; dy++) {
            float rin[NIN];
            {
                const float* tr = trow_base + dy * TIWP;
                float4 a = *reinterpret_cast<const float4*>(tr);
                rin[0] = a.x; rin[1] = a.y; rin[2] = a.z; rin[3] = a.w;
                if (STRIDE == 2) {
                    float4 e = *reinterpret_cast<const float4*>(tr + 4);
                    rin[4] = e.x; rin[5] = e.y; rin[6] = e.z; rin[7] = e.w;
                    float2 t = *reinterpret_cast<const float2*>(tr + 8);
                    rin[NIN - 2] = t.x; rin[NIN - 1] = t.y;
                } else {
                    float2 t = *reinterpret_cast<const float2*>(tr + 4);
                    rin[NIN - 2] = t.x; rin[NIN - 1] = t.y;
                }
            }

            #pragma unroll
            for (int kx = 0; kx < 3; kx++) {
                const int k = dy * 3 + kx;
                float4 wa = wk[k * 2 + 0];   // co 0..3 (broadcast LDS.128)
                float4 wb = wk[k * 2 + 1];   // co 4..7
                #pragma unroll
                for (int px = 0; px < 4; px++) {
                    const float v = rin[px * STRIDE + kx];
                    acc[0][px] = fmaf(v, wa.x, acc[0][px]);
                    acc[1][px] = fmaf(v, wa.y, acc[1][px]);
                    acc[2][px] = fmaf(v, wa.z, acc[2][px]);
                    acc[3][px] = fmaf(v, wa.w, acc[3][px]);
                    acc[4][px] = fmaf(v, wb.x, acc[4][px]);
                    acc[5][px] = fmaf(v, wb.y, acc[5][px]);
                    acc[6][px] = fmaf(v, wb.z, acc[6][px]);
                    acc[7][px] = fmaf(v, wb.w, acc[7][px]);
                }
            }
        }
    }

    const int oy = blockIdx.y * TH + ty;
    const int ox = blockIdx.x * TW + tx * 4;
    #pragma unroll
    for (int co = 0; co < COG; co++) {
        float4 v = make_float4(acc[co][0], acc[co][1], acc[co][2], acc[co][3]);
        if (do_relu) {
            v.x = fmaxf(v.x, 0.0f); v.y = fmaxf(v.y, 0.0f);
            v.z = fmaxf(v.z, 0.0f); v.w = fmaxf(v.w, 0.0f);
        }
        *reinterpret_cast<float4*>(
            out + (((size_t)b * Cout + g * COG + co) * Hout + oy) * Wout + ox) = v;
    }
}

// ---------------------------------------------------------------------------
// ConvOffset2D bilinear sampling (faithful torch-style raw reshape).
// H, W, C are powers of two -> shift/mask indexing (no div/mod).
// ---------------------------------------------------------------------------
__global__ void deform_kernel(const float* __restrict__ x,
                              const float* __restrict__ off,
                              float* __restrict__ out,
                              int wsh, int hsh, int csh, int total)
{
    int idx = blockIdx.x * blockDim.x + threadIdx.x;
    if (idx >= total) return;
    const int W = 1 << wsh, H = 1 << hsh, C = 1 << csh;
    int w = idx & (W - 1);
    int h = (idx >> wsh) & (H - 1);
    int c = (idx >> (wsh + hsh)) & (C - 1);
    int b = idx >> (wsh + hsh + csh);

    size_t HW = (size_t)H * W;
    size_t obase = ((size_t)((b << csh) + c) * 2) * HW + 2 * (size_t)((h << wsh) + w);
    float o0 = off[obase];
    float o1 = off[obase + 1];

    float r  = fminf(fmaxf(o0 + (float)h, 0.0f), (float)(H - 1));
    float cc = fminf(fmaxf(o1 + (float)w, 0.0f), (float)(W - 1));
    float r0f = floorf(r), c0f = floorf(cc);
    int r0 = (int)r0f;
    int r1 = (int)ceilf(r);
    int c0 = (int)c0f;
    int c1 = (int)ceilf(cc);

    const float* xb = x + (((size_t)(b << csh) + c)) * HW;
    float v_lt = xb[(r0 << wsh) + c0];
    float v_rb = xb[(r1 << wsh) + c1];
    float v_lb = xb[(r0 << wsh) + c1];
    float v_rt = xb[(r1 << wsh) + c0];
    float fr = r - r0f;
    float fc = cc - c0f;
    float vt = v_lt + (v_rt - v_lt) * fr;
    float vb = v_lb + (v_rb - v_lb) * fr;
    out[idx] = vt + (vb - vt) * fc;
}

// ---------------------------------------------------------------------------
// Global average pool over H*W. One block per (b, c).
// ---------------------------------------------------------------------------
__global__ void avgpool_kernel(const float* __restrict__ in,
                               float* __restrict__ out, int HW)
{
    const float* p = in + (size_t)blockIdx.x * HW;
    float s = 0.0f;
    for (int i = threadIdx.x; i < HW; i += blockDim.x) s += p[i];
    __shared__ float sm[256];
    sm[threadIdx.x] = s;
    __syncthreads();
    for (int st = 128; st > 0; st >>= 1) {
        if (threadIdx.x < st) sm[threadIdx.x] += sm[threadIdx.x + st];
        __syncthreads();
    }
    if (threadIdx.x == 0) out[blockIdx.x] = sm[0] / (float)HW;
}

// ---------------------------------------------------------------------------
// Launch pipeline (graph-capturable: kernel launches only).
// ---------------------------------------------------------------------------
extern "C" void kernel_launch(void* const* d_in, const int* in_sizes, int n_in,
                              void* d_out, int out_size)
{
    const float* x   = (const float*)d_in[0];
    const float* w1  = (const float*)d_in[1];
    const float* b1  = (const float*)d_in[2];
    const float* ow1 = (const float*)d_in[3];
    const float* w2  = (const float*)d_in[4];
    const float* b2  = (const float*)d_in[5];
    const float* ow2 = (const float*)d_in[6];
    const float* w3  = (const float*)d_in[7];
    const float* b3  = (const float*)d_in[8];
    const float* ow3 = (const float*)d_in[9];
    const float* w4  = (const float*)d_in[10];
    const float* b4  = (const float*)d_in[11];
    float* outp = (float*)d_out;

    float *A, *B, *C;
    cudaGetSymbolAddress((void**)&A, g_bufA);
    cudaGetSymbolAddress((void**)&B, g_bufB);
    cudaGetSymbolAddress((void**)&C, g_bufC);

    const dim3 blk(8, 16);

    // 1) conv1: x(16,32,256,256) -> A, relu
    conv3x3_kernel<1, 32><<<dim3(8, 16, 16 * 4), blk>>>(x, w1, b1, A, 32, 256, 256, 1);

    // 2) offconv1: A -> B (16,64,256,256)
    conv3x3_kernel<1, 32><<<dim3(8, 16, 16 * 8), blk>>>(A, ow1, nullptr, B, 64, 256, 256, 0);

    // 3) deform1: A,B -> C (16,32,256,256);  W=256,H=256,C=32
    {
        int total = 16 * 32 * 256 * 256;
        deform_kernel<<<total / 256, 256>>>(A, B, C, 8, 8, 5, total);
    }

    // 4) conv2 stride2: C -> A (16,64,128,128), relu
    conv3x3_kernel<2, 32><<<dim3(4, 8, 16 * 8), blk>>>(C, w2, b2, A, 64, 256, 256, 1);

    // 5) offconv2: A -> B (16,128,128,128)
    conv3x3_kernel<1, 64><<<dim3(4, 8, 16 * 16), blk>>>(A, ow2, nullptr, B, 128, 128, 128, 0);

    // 6) deform2: A,B -> C (16,64,128,128);  W=128,H=128,C=64
    {
        int total = 16 * 64 * 128 * 128;
        deform_kernel<<<total / 256, 256>>>(A, B, C, 7, 7, 6, total);
    }

    // 7) conv3 stride2: C -> A (16,32,64,64), relu
    conv3x3_kernel<2, 64><<<dim3(2, 4, 16 * 4), blk>>>(C, w3, b3, A, 32, 128, 128, 1);

    // 8) offconv3: A -> B (16,64,64,64)
    conv3x3_kernel<1, 32><<<dim3(2, 4, 16 * 8), blk>>>(A, ow3, nullptr, B, 64, 64, 64, 0);

    // 9) deform3: A,B -> C (16,32,64,64);  W=64,H=64,C=32
    {
        int total = 16 * 32 * 64 * 64;
        deform_kernel<<<total / 256, 256>>>(A, B, C, 6, 6, 5, total);
    }

    // 10) conv4 stride2: C -> A (16,32,32,32), relu
    conv3x3_kernel<2, 32><<<dim3(1, 2, 16 * 4), blk>>>(C, w4, b4, A, 32, 64, 64, 1);

    // 11) global avg pool -> (16,32,1,1)
    avgpool_kernel<<<512, 256>>>(A, outp, 32 * 32);
}

// round 4
// speedup vs baseline: 1.5668x; 1.5492x over previous
#include <cuda_runtime.h>
#include <cstdint>

// ---------------------------------------------------------------------------
// Scratch buffers (static __device__ globals — no allocation allowed).
// ---------------------------------------------------------------------------
__device__ float g_bufA[33554432];
__device__ float g_bufB[67108864];
__device__ float g_bufC[33554432];

// ---------------------------------------------------------------------------
// tf32 helpers
// ---------------------------------------------------------------------------
__device__ __forceinline__ float tf32r(float x)
{
    uint32_t u;
    asm("cvt.rna.tf32.f32 %0, %1;" : "=r"(u) : "f"(x));
    return __uint_as_float(u);
}

__device__ __forceinline__ void mma_tf32(float* c,
                                         uint32_t a0, uint32_t a1,
                                         uint32_t a2, uint32_t a3,
                                         uint32_t b0, uint32_t b1)
{
    asm volatile(
        "mma.sync.aligned.m16n8k8.row.col.f32.tf32.tf32.f32 "
        "{%0,%1,%2,%3}, {%4,%5,%6,%7}, {%8,%9}, {%0,%1,%2,%3};\n"
        : "+f"(c[0]), "+f"(c[1]), "+f"(c[2]), "+f"(c[3])
        : "r"(a0), "r"(a1), "r"(a2), "r"(a3), "r"(b0), "r"(b1));
}

// ---------------------------------------------------------------------------
// Implicit-GEMM 3x3 conv (pad=1) with tf32 mma.sync.m16n8k8.
// D[co, px] = sum_k W[co,k] * Im2col[k,px],  k = ci*9 + dy*3 + dx.
//
// Block = 256 threads (8 warps). Output tile: 32 couts x (4 h x 32 w) px.
//   warp wid: mh = wid&1 selects co half (16), nq = wid>>1 selects out-row.
//   Each warp: 16 co x 32 px = 4 mma n-tiles of 8 consecutive w.
// K loop: ci-chunks of 8 -> 72 k = 9 k-steps of 8.
//   Input tile (halo incl.) for the chunk staged in smem; B fragments
//   gathered via koff[k] table. Weights staged as [32co][stride 76].
// All layer dims divide the tile sizes exactly -> no output masking.
// ---------------------------------------------------------------------------
template<int STRIDE, int CIN, int BR>
__global__ __launch_bounds__(256)
void conv3x3_tc(const float* __restrict__ in, const float* __restrict__ w,
                const float* __restrict__ bias, float* __restrict__ out,
                int Cout, int Hin, int Win)
{
    constexpr int TIH  = 4 * STRIDE + 2;           // 6 / 10
    constexpr int TIW  = 32 * STRIDE + 2;          // 34 / 66
    constexpr int TIWP = (TIW + 3) & ~3;           // 36 / 68
    constexpr int CHE  = TIH * TIWP;               // per-ci tile elems
    constexpr int CHUNK = 8;
    constexpr int NCH  = CIN / CHUNK;
    constexpr int KC   = CHUNK * 9;                // 72
    constexpr int WSTR = 76;                       // conflict-free A stride

    __shared__ float s_tile[CHUNK * CHE];
    __shared__ float s_w[32 * WSTR];
    __shared__ int   s_koff[KC];

    const int Hout = Hin / STRIDE, Wout = Win / STRIDE;
    const int tid = threadIdx.x;
    const int groups = Cout >> 5;
    const int g  = blockIdx.z % groups;
    const int b  = blockIdx.z / groups;
    const int bx = blockIdx.x, by = blockIdx.y;

    if (tid < KC) {
        int ci8 = tid / 9, r = tid % 9;
        s_koff[tid] = ci8 * CHE + (r / 3) * TIWP + (r % 3);
    }

    const int lane = tid & 31, wid = tid >> 5;
    const int tig = lane & 3, gid = lane >> 2;
    const int mh = wid & 1;        // co half
    const int nq = wid >> 1;       // out-row within 4-row tile

    float acc[4][4];
    {
        float bv0 = 0.0f, bv1 = 0.0f;
        if (BR) {
            bv0 = bias[g * 32 + mh * 16 + gid];
            bv1 = bias[g * 32 + mh * 16 + gid + 8];
        }
        #pragma unroll
        for (int t = 0; t < 4; t++) {
            acc[t][0] = bv0; acc[t][1] = bv0;
            acc[t][2] = bv1; acc[t][3] = bv1;
        }
    }

    const int y0 = by * 4 * STRIDE - 1;
    const int x0 = bx * 32 * STRIDE - 1;

    for (int ch = 0; ch < NCH; ch++) {
        __syncthreads();
        // Stage weight chunk: [32 co][72 k] -> s_w[co*WSTR + j]
        {
            const float* wsrc = w + ((size_t)(g * 32) * CIN + ch * CHUNK) * 9;
            #pragma unroll
            for (int i = tid; i < 32 * KC; i += 256) {
                int co = i / KC, j = i - co * KC;
                s_w[co * WSTR + j] = tf32r(wsrc[(size_t)co * CIN * 9 + j]);
            }
        }
        // Stage input tile chunk (with halo, zero-padded OOB)
        {
            const float* isrc = in + ((size_t)b * CIN + ch * CHUNK) * ((size_t)Hin * Win);
            #pragma unroll
            for (int i = tid; i < CHUNK * CHE; i += 256) {
                int ci8 = i / CHE, rem = i - ci8 * CHE;
                int r = rem / TIWP, cx = rem - r * TIWP;
                int gy = y0 + r, gx = x0 + cx;
                float v = 0.0f;
                if (gy >= 0 && gy < Hin && gx >= 0 && gx < Win && cx < TIW)
                    v = isrc[(size_t)ci8 * Hin * Win + (size_t)gy * Win + gx];
                s_tile[i] = tf32r(v);
            }
        }
        __syncthreads();

        const int bb = nq * STRIDE * TIWP + gid * STRIDE;
        #pragma unroll
        for (int ks = 0; ks < 9; ks++) {
            const int ko1 = s_koff[ks * 8 + tig];
            const int ko2 = s_koff[ks * 8 + tig + 4];
            const float* ap = s_w + (mh * 16 + gid) * WSTR + ks * 8 + tig;
            uint32_t a0 = __float_as_uint(ap[0]);
            uint32_t a1 = __float_as_uint(ap[8 * WSTR]);
            uint32_t a2 = __float_as_uint(ap[4]);
            uint32_t a3 = __float_as_uint(ap[8 * WSTR + 4]);
            #pragma unroll
            for (int t = 0; t < 4; t++) {
                uint32_t b0 = __float_as_uint(s_tile[ko1 + bb + t * 8 * STRIDE]);
                uint32_t b1 = __float_as_uint(s_tile[ko2 + bb + t * 8 * STRIDE]);
                mma_tf32(acc[t], a0, a1, a2, a3, b0, b1);
            }
        }
    }

    // Epilogue: c0:(gid, 2tig) c1:(gid, 2tig+1) c2:(gid+8, 2tig) c3:(gid+8, 2tig+1)
    const int co0 = g * 32 + mh * 16 + gid;
    const int h = by * 4 + nq;
    #pragma unroll
    for (int t = 0; t < 4; t++) {
        float2 lo = make_float2(acc[t][0], acc[t][1]);
        float2 hi = make_float2(acc[t][2], acc[t][3]);
        if (BR) {
            lo.x = fmaxf(lo.x, 0.0f); lo.y = fmaxf(lo.y, 0.0f);
            hi.x = fmaxf(hi.x, 0.0f); hi.y = fmaxf(hi.y, 0.0f);
        }
        const int wg = bx * 32 + t * 8 + 2 * tig;
        *reinterpret_cast<float2*>(
            out + (((size_t)b * Cout + co0) * Hout + h) * Wout + wg) = lo;
        *reinterpret_cast<float2*>(
            out + (((size_t)b * Cout + co0 + 8) * Hout + h) * Wout + wg) = hi;
    }
}

// ---------------------------------------------------------------------------
// ConvOffset2D bilinear sampling (faithful torch-style raw reshape).
// H, W, C powers of two -> shift/mask indexing.
// ---------------------------------------------------------------------------
__global__ void deform_kernel(const float* __restrict__ x,
                              const float* __restrict__ off,
                              float* __restrict__ out,
                              int wsh, int hsh, int csh, int total)
{
    int idx = blockIdx.x * blockDim.x + threadIdx.x;
    if (idx >= total) return;
    const int W = 1 << wsh, H = 1 << hsh, C = 1 << csh;
    int w = idx & (W - 1);
    int h = (idx >> wsh) & (H - 1);
    int c = (idx >> (wsh + hsh)) & (C - 1);
    int b = idx >> (wsh + hsh + csh);

    size_t HW = (size_t)H * W;
    size_t obase = ((size_t)((b << csh) + c) * 2) * HW + 2 * (size_t)((h << wsh) + w);
    float o0 = off[obase];
    float o1 = off[obase + 1];

    float r  = fminf(fmaxf(o0 + (float)h, 0.0f), (float)(H - 1));
    float cc = fminf(fmaxf(o1 + (float)w, 0.0f), (float)(W - 1));
    float r0f = floorf(r), c0f = floorf(cc);
    int r0 = (int)r0f;
    int r1 = (int)ceilf(r);
    int c0 = (int)c0f;
    int c1 = (int)ceilf(cc);

    const float* xb = x + (((size_t)(b << csh) + c)) * HW;
    float v_lt = xb[(r0 << wsh) + c0];
    float v_rb = xb[(r1 << wsh) + c1];
    float v_lb = xb[(r0 << wsh) + c1];
    float v_rt = xb[(r1 << wsh) + c0];
    float fr = r - r0f;
    float fc = cc - c0f;
    float vt = v_lt + (v_rt - v_lt) * fr;
    float vb = v_lb + (v_rb - v_lb) * fr;
    out[idx] = vt + (vb - vt) * fc;
}

// ---------------------------------------------------------------------------
// Global average pool over H*W. One block per (b, c).
// ---------------------------------------------------------------------------
__global__ void avgpool_kernel(const float* __restrict__ in,
                               float* __restrict__ out, int HW)
{
    const float* p = in + (size_t)blockIdx.x * HW;
    float s = 0.0f;
    for (int i = threadIdx.x; i < HW; i += blockDim.x) s += p[i];
    __shared__ float sm[256];
    sm[threadIdx.x] = s;
    __syncthreads();
    for (int st = 128; st > 0; st >>= 1) {
        if (threadIdx.x < st) sm[threadIdx.x] += sm[threadIdx.x + st];
        __syncthreads();
    }
    if (threadIdx.x == 0) out[blockIdx.x] = sm[0] / (float)HW;
}

// ---------------------------------------------------------------------------
// Launch pipeline (graph-capturable: kernel launches only).
// ---------------------------------------------------------------------------
extern "C" void kernel_launch(void* const* d_in, const int* in_sizes, int n_in,
                              void* d_out, int out_size)
{
    const float* x   = (const float*)d_in[0];
    const float* w1  = (const float*)d_in[1];
    const float* b1  = (const float*)d_in[2];
    const float* ow1 = (const float*)d_in[3];
    const float* w2  = (const float*)d_in[4];
    const float* b2  = (const float*)d_in[5];
    const float* ow2 = (const float*)d_in[6];
    const float* w3  = (const float*)d_in[7];
    const float* b3  = (const float*)d_in[8];
    const float* ow3 = (const float*)d_in[9];
    const float* w4  = (const float*)d_in[10];
    const float* b4  = (const float*)d_in[11];
    float* outp = (float*)d_out;

    float *A, *B, *C;
    cudaGetSymbolAddress((void**)&A, g_bufA);
    cudaGetSymbolAddress((void**)&B, g_bufB);
    cudaGetSymbolAddress((void**)&C, g_bufC);

    // 1) conv1: x(16,32,256,256) -> A (16,32,256,256), bias+relu
    conv3x3_tc<1, 32, 1><<<dim3(8, 64, 16), 256>>>(x, w1, b1, A, 32, 256, 256);

    // 2) offconv1: A -> B (16,64,256,256), no bias/relu
    conv3x3_tc<1, 32, 0><<<dim3(8, 64, 32), 256>>>(A, ow1, nullptr, B, 64, 256, 256);

    // 3) deform1: A,B -> C (16,32,256,256)
    {
        int total = 16 * 32 * 256 * 256;
        deform_kernel<<<total / 256, 256>>>(A, B, C, 8, 8, 5, total);
    }

    // 4) conv2 stride2: C -> A (16,64,128,128), bias+relu
    conv3x3_tc<2, 32, 1><<<dim3(4, 32, 32), 256>>>(C, w2, b2, A, 64, 256, 256);

    // 5) offconv2: A -> B (16,128,128,128)
    conv3x3_tc<1, 64, 0><<<dim3(4, 32, 64), 256>>>(A, ow2, nullptr, B, 128, 128, 128);

    // 6) deform2: A,B -> C (16,64,128,128)
    {
        int total = 16 * 64 * 128 * 128;
        deform_kernel<<<total / 256, 256>>>(A, B, C, 7, 7, 6, total);
    }

    // 7) conv3 stride2: C -> A (16,32,64,64), bias+relu
    conv3x3_tc<2, 64, 1><<<dim3(2, 16, 16), 256>>>(C, w3, b3, A, 32, 128, 128);

    // 8) offconv3: A -> B (16,64,64,64)
    conv3x3_tc<1, 32, 0><<<dim3(2, 16, 32), 256>>>(A, ow3, nullptr, B, 64, 64, 64);

    // 9) deform3: A,B -> C (16,32,64,64)
    {
        int total = 16 * 32 * 64 * 64;
        deform_kernel<<<total / 256, 256>>>(A, B, C, 6, 6, 5, total);
    }

    // 10) conv4 stride2: C -> A (16,32,32,32), bias+relu
    conv3x3_tc<2, 32, 1><<<dim3(1, 8, 16), 256>>>(C, w4, b4, A, 32, 64, 64);

    // 11) global avg pool -> (16,32,1,1)
    avgpool_kernel<<<512, 256>>>(A, outp, 32 * 32);
}

// round 5
// speedup vs baseline: 3.0642x; 1.9558x over previous
#include <cuda_runtime.h>
#include <cstdint>

// ---------------------------------------------------------------------------
// Scratch buffers (static __device__ globals — no allocation allowed).
// ---------------------------------------------------------------------------
__device__ float g_bufA[33554432];
__device__ float g_bufB[67108864];
__device__ float g_bufC[33554432];
__device__ float g_wt[262144];          // tf32-rounded weights

// ---------------------------------------------------------------------------
// Helpers
// ---------------------------------------------------------------------------
__device__ __forceinline__ float tf32r(float x)
{
    uint32_t u;
    asm("cvt.rna.tf32.f32 %0, %1;" : "=r"(u) : "f"(x));
    return __uint_as_float(u);
}

__device__ __forceinline__ void mma_tf32(float* c,
                                         uint32_t a0, uint32_t a1,
                                         uint32_t a2, uint32_t a3,
                                         uint32_t b0, uint32_t b1)
{
    asm volatile(
        "mma.sync.aligned.m16n8k8.row.col.f32.tf32.tf32.f32 "
        "{%0,%1,%2,%3}, {%4,%5,%6,%7}, {%8,%9}, {%0,%1,%2,%3};\n"
        : "+f"(c[0]), "+f"(c[1]), "+f"(c[2]), "+f"(c[3])
        : "r"(a0), "r"(a1), "r"(a2), "r"(a3), "r"(b0), "r"(b1));
}

__device__ __forceinline__ uint32_t smem_u32(const void* p)
{
    return (uint32_t)__cvta_generic_to_shared(p);
}

// 16B cp.async with zero-fill when !ok (src-size = 0 -> no bytes read).
__device__ __forceinline__ void cp16z(uint32_t dst, const float* src, bool ok)
{
    int sz = ok ? 16 : 0;
    asm volatile("cp.async.ca.shared.global [%0], [%1], 16, %2;"
                 :: "r"(dst), "l"(src), "r"(sz));
}

// ---------------------------------------------------------------------------
// Implicit-GEMM 3x3 conv (pad=1), tf32 mma.sync.m16n8k8, cp.async
// double-buffered K-chunk pipeline. Inputs/weights are PRE-ROUNDED to tf32.
//
// Block = 256 thr (8 warps). Output tile: 32 couts x (4h x 32w).
//   warp: mh=wid&1 -> co half (16), nq=wid>>1 -> out row.
// K = CIN*9 in ci-chunks of 8 (72 k = 9 k-steps of 8).
// Input tile left halo widened to 4 cols so gmem row segments are 16B-aligned.
// ---------------------------------------------------------------------------
template<int STRIDE, int CIN, int BR>
__global__ __launch_bounds__(256, 2)
void conv3x3_tc(const float* __restrict__ in, const float* __restrict__ w,
                const float* __restrict__ bias, float* __restrict__ out,
                int Cout, int Hin, int Win)
{
    constexpr int TH = 4, TW = 32;
    constexpr int TIH  = TH * STRIDE + 2;               // 6 / 10
    constexpr int TIWP = (TW * STRIDE + 5 + 3) & ~3;    // 40 / 72
    constexpr int RU   = TIWP / 4;                      // 16B units per row
    constexpr int CHE  = TIH * TIWP;
    constexpr int TILE_N = 8 * CHE;
    constexpr int NCH  = CIN / 8;
    constexpr int WSTR = 76;
    constexpr int WN   = 32 * WSTR;                     // 2432

    extern __shared__ __align__(16) float smem[];
    // layout: [tile0 | tile1 | w0 | w1]
    __shared__ int s_koff[72];

    const int Hout = Hin / STRIDE, Wout = Win / STRIDE;
    const int tid = threadIdx.x;
    const int groups = Cout >> 5;
    const int g  = blockIdx.z % groups;
    const int b  = blockIdx.z / groups;
    const int bx = blockIdx.x, by = blockIdx.y;

    if (tid < 72) {
        int ci8 = tid / 9, r = tid % 9;
        s_koff[tid] = ci8 * CHE + (r / 3) * TIWP + (r % 3);
    }

    const int y0 = by * TH * STRIDE - 1;
    const int x0 = bx * TW * STRIDE - 4;    // 16B-aligned halo (logical -1 = col 3)
    const size_t HW = (size_t)Hin * Win;
    const float* ibase = in + (size_t)b * CIN * HW;
    const float* wbase = w + (size_t)(g * 32) * CIN * 9;

    auto load_chunk = [&](int ch, int bi) {
        const float* isrc = ibase + (size_t)(ch * 8) * HW;
        uint32_t tdst = smem_u32(smem + bi * TILE_N);
        constexpr int TU = 8 * TIH * RU;
        for (int u = tid; u < TU; u += 256) {
            int ci8 = u / (TIH * RU);
            int rem = u - ci8 * (TIH * RU);
            int r = rem / RU, uu = rem - r * RU;
            int gy = y0 + r, gx = x0 + 4 * uu;
            bool ok = (gy >= 0) && (gy < Hin) && (gx >= 0) && (gx < Win);
            cp16z(tdst + 4u * (uint32_t)(ci8 * CHE + r * TIWP + 4 * uu),
                  isrc + (size_t)ci8 * HW + (size_t)gy * Win + gx, ok);
        }
        const float* wsrc = wbase + ch * 72;
        uint32_t wdst = smem_u32(smem + 2 * TILE_N + bi * WN);
        for (int u = tid; u < 32 * 18; u += 256) {
            int co = u / 18, k4 = u - co * 18;
            cp16z(wdst + 4u * (uint32_t)(co * WSTR + 4 * k4),
                  wsrc + (size_t)co * CIN * 9 + 4 * k4, true);
        }
        asm volatile("cp.async.commit_group;");
    };

    const int lane = tid & 31, wid = tid >> 5;
    const int tig = lane & 3, gid = lane >> 2;
    const int mh = wid & 1;
    const int nq = wid >> 1;

    float acc[4][4];
    {
        float bv0 = 0.0f, bv1 = 0.0f;
        if (BR) {
            bv0 = bias[g * 32 + mh * 16 + gid];
            bv1 = bias[g * 32 + mh * 16 + gid + 8];
        }
        #pragma unroll
        for (int t = 0; t < 4; t++) {
            acc[t][0] = bv0; acc[t][1] = bv0;
            acc[t][2] = bv1; acc[t][3] = bv1;
        }
    }

    load_chunk(0, 0);

    for (int ch = 0; ch < NCH; ch++) {
        const int cur = ch & 1;
        if (ch + 1 < NCH) {
            load_chunk(ch + 1, cur ^ 1);
            asm volatile("cp.async.wait_group 1;");
        } else {
            asm volatile("cp.async.wait_group 0;");
        }
        __syncthreads();

        const float* st = smem + cur * TILE_N;
        const float* sw = smem + 2 * TILE_N + cur * WN;
        const int bb = nq * STRIDE * TIWP + gid * STRIDE + 3;

        #pragma unroll
        for (int ks = 0; ks < 9; ks++) {
            const int ko1 = s_koff[ks * 8 + tig];
            const int ko2 = s_koff[ks * 8 + tig + 4];
            const float* ap = sw + (mh * 16 + gid) * WSTR + ks * 8 + tig;
            uint32_t a0 = __float_as_uint(ap[0]);
            uint32_t a1 = __float_as_uint(ap[8 * WSTR]);
            uint32_t a2 = __float_as_uint(ap[4]);
            uint32_t a3 = __float_as_uint(ap[8 * WSTR + 4]);
            #pragma unroll
            for (int t = 0; t < 4; t++) {
                uint32_t b0 = __float_as_uint(st[ko1 + bb + t * 8 * STRIDE]);
                uint32_t b1 = __float_as_uint(st[ko2 + bb + t * 8 * STRIDE]);
                mma_tf32(acc[t], a0, a1, a2, a3, b0, b1);
            }
        }
        __syncthreads();
    }

    // Epilogue (outputs rounded to tf32 so consumers can cp.async raw).
    const int co0 = g * 32 + mh * 16 + gid;
    const int h = by * TH + nq;
    #pragma unroll
    for (int t = 0; t < 4; t++) {
        float2 lo, hi;
        if (BR) {
            lo = make_float2(tf32r(fmaxf(acc[t][0], 0.0f)), tf32r(fmaxf(acc[t][1], 0.0f)));
            hi = make_float2(tf32r(fmaxf(acc[t][2], 0.0f)), tf32r(fmaxf(acc[t][3], 0.0f)));
        } else {
            lo = make_float2(tf32r(acc[t][0]), tf32r(acc[t][1]));
            hi = make_float2(tf32r(acc[t][2]), tf32r(acc[t][3]));
        }
        const int wg = bx * 32 + t * 8 + 2 * tig;
        *reinterpret_cast<float2*>(
            out + (((size_t)b * Cout + co0) * Hout + h) * Wout + wg) = lo;
        *reinterpret_cast<float2*>(
            out + (((size_t)b * Cout + co0 + 8) * Hout + h) * Wout + wg) = hi;
    }
}

// ---------------------------------------------------------------------------
// ConvOffset2D bilinear sampling (faithful torch-style raw reshape).
// Output rounded to tf32 (consumed raw by the next conv).
// ---------------------------------------------------------------------------
__global__ void deform_kernel(const float* __restrict__ x,
                              const float* __restrict__ off,
                              float* __restrict__ out,
                              int wsh, int hsh, int csh, int total)
{
    int idx = blockIdx.x * blockDim.x + threadIdx.x;
    if (idx >= total) return;
    const int W = 1 << wsh, H = 1 << hsh, C = 1 << csh;
    int w = idx & (W - 1);
    int h = (idx >> wsh) & (H - 1);
    int c = (idx >> (wsh + hsh)) & (C - 1);
    int b = idx >> (wsh + hsh + csh);

    size_t HW = (size_t)H * W;
    size_t obase = ((size_t)((b << csh) + c) * 2) * HW + 2 * (size_t)((h << wsh) + w);
    float o0 = off[obase];
    float o1 = off[obase + 1];

    float r  = fminf(fmaxf(o0 + (float)h, 0.0f), (float)(H - 1));
    float cc = fminf(fmaxf(o1 + (float)w, 0.0f), (float)(W - 1));
    float r0f = floorf(r), c0f = floorf(cc);
    int r0 = (int)r0f;
    int r1 = (int)ceilf(r);
    int c0 = (int)c0f;
    int c1 = (int)ceilf(cc);

    const float* xb = x + (((size_t)(b << csh) + c)) * HW;
    float v_lt = xb[(r0 << wsh) + c0];
    float v_rb = xb[(r1 << wsh) + c1];
    float v_lb = xb[(r0 << wsh) + c1];
    float v_rt = xb[(r1 << wsh) + c0];
    float fr = r - r0f;
    float fc = cc - c0f;
    float vt = v_lt + (v_rt - v_lt) * fr;
    float vb = v_lb + (v_rb - v_lb) * fr;
    out[idx] = tf32r(vt + (vb - vt) * fc);
}

// ---------------------------------------------------------------------------
// tf32 rounding prepass (vectorized).
// ---------------------------------------------------------------------------
__global__ void cvt4_kernel(const float4* __restrict__ src,
                            float4* __restrict__ dst, int n4)
{
    int i = blockIdx.x * 256 + threadIdx.x;
    if (i >= n4) return;
    float4 v = src[i];
    v.x = tf32r(v.x); v.y = tf32r(v.y); v.z = tf32r(v.z); v.w = tf32r(v.w);
    dst[i] = v;
}

// ---------------------------------------------------------------------------
// Global average pool over H*W. One block per (b, c).
// ---------------------------------------------------------------------------
__global__ void avgpool_kernel(const float* __restrict__ in,
                               float* __restrict__ out, int HW)
{
    const float* p = in + (size_t)blockIdx.x * HW;
    float s = 0.0f;
    for (int i = threadIdx.x; i < HW; i += blockDim.x) s += p[i];
    __shared__ float sm[256];
    sm[threadIdx.x] = s;
    __syncthreads();
    for (int st = 128; st > 0; st >>= 1) {
        if (threadIdx.x < st) sm[threadIdx.x] += sm[threadIdx.x + st];
        __syncthreads();
    }
    if (threadIdx.x == 0) out[blockIdx.x] = sm[0] / (float)HW;
}

// ---------------------------------------------------------------------------
// Launch pipeline (graph-capturable: kernel launches + attribute sets only).
// ---------------------------------------------------------------------------
static inline int conv_smem_bytes(int stride)
{
    int tih  = 4 * stride + 2;
    int tiwp = (32 * stride + 5 + 3) & ~3;
    int tile_n = 8 * tih * tiwp;
    return (2 * tile_n + 2 * (32 * 76)) * 4;   // 34816 (s1) / 65536 (s2)
}

extern "C" void kernel_launch(void* const* d_in, const int* in_sizes, int n_in,
                              void* d_out, int out_size)
{
    const float* x   = (const float*)d_in[0];
    const float* w1  = (const float*)d_in[1];
    const float* b1  = (const float*)d_in[2];
    const float* ow1 = (const float*)d_in[3];
    const float* w2  = (const float*)d_in[4];
    const float* b2  = (const float*)d_in[5];
    const float* ow2 = (const float*)d_in[6];
    const float* w3  = (const float*)d_in[7];
    const float* b3  = (const float*)d_in[8];
    const float* ow3 = (const float*)d_in[9];
    const float* w4  = (const float*)d_in[10];
    const float* b4  = (const float*)d_in[11];
    float* outp = (float*)d_out;

    float *A, *B, *C, *WT;
    cudaGetSymbolAddress((void**)&A, g_bufA);
    cudaGetSymbolAddress((void**)&B, g_bufB);
    cudaGetSymbolAddress((void**)&C, g_bufC);
    cudaGetSymbolAddress((void**)&WT, g_wt);

    const int S1 = conv_smem_bytes(1), S2 = conv_smem_bytes(2);
    cudaFuncSetAttribute(conv3x3_tc<1, 32, 1>, cudaFuncAttributeMaxDynamicSharedMemorySize, S1);
    cudaFuncSetAttribute(conv3x3_tc<1, 32, 0>, cudaFuncAttributeMaxDynamicSharedMemorySize, S1);
    cudaFuncSetAttribute(conv3x3_tc<1, 64, 0>, cudaFuncAttributeMaxDynamicSharedMemorySize, S1);
    cudaFuncSetAttribute(conv3x3_tc<2, 32, 1>, cudaFuncAttributeMaxDynamicSharedMemorySize, S2);
    cudaFuncSetAttribute(conv3x3_tc<2, 64, 1>, cudaFuncAttributeMaxDynamicSharedMemorySize, S2);

    // tf32-rounded weight copies in g_wt
    float* w1t  = WT;             // 9216
    float* ow1t = WT + 9216;      // 18432
    float* w2t  = WT + 27648;     // 18432
    float* ow2t = WT + 46080;     // 73728
    float* w3t  = WT + 119808;    // 18432
    float* ow3t = WT + 138240;    // 18432
    float* w4t  = WT + 156672;    // 9216

    auto cvt = [](const float* s, float* d, int n) {
        cvt4_kernel<<<(n / 4 + 255) / 256, 256>>>((const float4*)s, (float4*)d, n / 4);
    };
    cvt(w1, w1t, 9216);   cvt(ow1, ow1t, 18432);
    cvt(w2, w2t, 18432);  cvt(ow2, ow2t, 73728);
    cvt(w3, w3t, 18432);  cvt(ow3, ow3t, 18432);
    cvt(w4, w4t, 9216);
    cvt(x, C, 16 * 32 * 256 * 256);   // x~ -> C (free until deform1 writes it)

    // 1) conv1: C(x~) -> A (16,32,256,256), bias+relu
    conv3x3_tc<1, 32, 1><<<dim3(8, 64, 16), 256, S1>>>(C, w1t, b1, A, 32, 256, 256);

    // 2) offconv1: A -> B (16,64,256,256)
    conv3x3_tc<1, 32, 0><<<dim3(8, 64, 32), 256, S1>>>(A, ow1t, nullptr, B, 64, 256, 256);

    // 3) deform1: A,B -> C (16,32,256,256)
    {
        int total = 16 * 32 * 256 * 256;
        deform_kernel<<<total / 256, 256>>>(A, B, C, 8, 8, 5, total);
    }

    // 4) conv2 stride2: C -> A (16,64,128,128), bias+relu
    conv3x3_tc<2, 32, 1><<<dim3(4, 32, 32), 256, S2>>>(C, w2t, b2, A, 64, 256, 256);

    // 5) offconv2: A -> B (16,128,128,128)
    conv3x3_tc<1, 64, 0><<<dim3(4, 32, 64), 256, S1>>>(A, ow2t, nullptr, B, 128, 128, 128);

    // 6) deform2: A,B -> C (16,64,128,128)
    {
        int total = 16 * 64 * 128 * 128;
        deform_kernel<<<total / 256, 256>>>(A, B, C, 7, 7, 6, total);
    }

    // 7) conv3 stride2: C -> A (16,32,64,64), bias+relu
    conv3x3_tc<2, 64, 1><<<dim3(2, 16, 16), 256, S2>>>(C, w3t, b3, A, 32, 128, 128);

    // 8) offconv3: A -> B (16,64,64,64)
    conv3x3_tc<1, 32, 0><<<dim3(2, 16, 32), 256, S1>>>(A, ow3t, nullptr, B, 64, 64, 64);

    // 9) deform3: A,B -> C (16,32,64,64)
    {
        int total = 16 * 32 * 64 * 64;
        deform_kernel<<<total / 256, 256>>>(A, B, C, 6, 6, 5, total);
    }

    // 10) conv4 stride2: C -> A (16,32,32,32), bias+relu
    conv3x3_tc<2, 32, 1><<<dim3(1, 8, 16), 256, S2>>>(C, w4t, b4, A, 32, 64, 64);

    // 11) global avg pool -> (16,32,1,1)
    avgpool_kernel<<<512, 256>>>(A, outp, 32 * 32);
}